// round 2
// baseline (speedup 1.0000x reference)
#include <cuda_runtime.h>
#include <math.h>

#define N_USERS 50000
#define N_ITEMS 100000
#define NN      150000
#define D       64
#define NINT    128
#define TSZ     32
#define BB      4096
#define EE      3150000
#define NB      147            // ceil(NN/1024)
#define TEMP_INV 5.0f
#define KL_REG  0.01
#define EMB_REG 1e-5
#define INT_REG 1e-5
#define SSL_REG 0.1

// ---------------- scratch (static device globals; no runtime alloc) ----------------
__device__ int    g_deg[NN];
__device__ int    g_rowptr[NN + 1];
__device__ int    g_cursor[NN];
__device__ int    g_bsums[256];
__device__ float  g_dinv[NN];
__device__ int    g_tsorted[EE];
__device__ float  g_gsorted[EE];
__device__ float  g_bufA[NN * D];
__device__ float  g_bufB[NN * D];
__device__ float  g_acc[NN * D];
__device__ float  g_e1u[BB * D], g_e2u[BB * D], g_e1i[BB * D], g_e2i[BB * D];
__device__ double g_sums[8];   // 0:kl 1:bpr 2:emb 3:int 4:nce_u 5:nce_i

// ---------------- init ----------------
__global__ void k_init() {
    int i = blockIdx.x * blockDim.x + threadIdx.x;
    if (i < NN) g_deg[i] = 0;
    if (i < 8)  g_sums[i] = 0.0;
}

// ---------------- degree ----------------
__global__ void k_deg(const int* __restrict__ h) {
    int i = blockIdx.x * blockDim.x + threadIdx.x;
    if (i < EE) atomicAdd(&g_deg[h[i]], 1);
}

// ---------------- 2-level exclusive scan ----------------
__global__ void k_scan1() {
    __shared__ int s[1024];
    int idx = blockIdx.x * 1024 + threadIdx.x;
    int v = (idx < NN) ? g_deg[idx] : 0;
    s[threadIdx.x] = v;
    __syncthreads();
    for (int off = 1; off < 1024; off <<= 1) {
        int t = (threadIdx.x >= off) ? s[threadIdx.x - off] : 0;
        __syncthreads();
        s[threadIdx.x] += t;
        __syncthreads();
    }
    if (idx < NN) g_rowptr[idx] = s[threadIdx.x] - v;   // block-local exclusive
    if (threadIdx.x == 1023) g_bsums[blockIdx.x] = s[1023];
}

__global__ void k_scan2() {
    if (threadIdx.x == 0) {
        int run = 0;
        for (int i = 0; i < NB; i++) { int v = g_bsums[i]; g_bsums[i] = run; run += v; }
    }
}

__global__ void k_scan3() {
    int i = blockIdx.x * blockDim.x + threadIdx.x;
    if (i < NN) {
        int rp = g_rowptr[i] + g_bsums[i >> 10];
        g_rowptr[i] = rp;
        g_cursor[i] = rp;
        g_dinv[i]   = 1.0f / sqrtf((float)g_deg[i]);
        if (i == 0) g_rowptr[NN] = EE;
    }
}

// ---------------- CSR scatter ----------------
__global__ void k_scatter(const int* __restrict__ h, const int* __restrict__ t) {
    int i = blockIdx.x * blockDim.x + threadIdx.x;
    if (i < EE) {
        int hh = h[i], tt = t[i];
        int pos = atomicAdd(&g_cursor[hh], 1);
        g_tsorted[pos] = tt;
        g_gsorted[pos] = g_dinv[hh] * g_dinv[tt];
    }
}

// ---------------- ego init: cur = acc = concat(user_emb, item_emb) ----------------
__global__ void k_initemb(const float* __restrict__ ue, const float* __restrict__ ie) {
    int i = blockIdx.x * blockDim.x + threadIdx.x;
    if (i < NN * D) {
        float v = (i < N_USERS * D) ? ue[i] : ie[i - N_USERS * D];
        g_bufA[i] = v;
        g_acc[i]  = v;
    }
}

// ---------------- propagation: warp per node, float2 per lane ----------------
__global__ void k_prop(int which) {
    int warp = (blockIdx.x * blockDim.x + threadIdx.x) >> 5;
    int lane = threadIdx.x & 31;
    if (warp >= NN) return;
    const float* __restrict__ cur = which ? g_bufB : g_bufA;
    float* __restrict__ nxt       = which ? g_bufA : g_bufB;
    int beg = g_rowptr[warp], end = g_rowptr[warp + 1];
    float a0 = 0.f, a1 = 0.f;
    for (int e = beg; e < end; e++) {
        int   t = g_tsorted[e];
        float g = g_gsorted[e];
        float2 v = *(const float2*)&cur[t * D + lane * 2];
        a0 += g * v.x;
        a1 += g * v.y;
    }
    int o = warp * D + lane * 2;
    nxt[o] = a0; nxt[o + 1] = a1;
    g_acc[o] += a0; g_acc[o + 1] += a1;
}

__device__ __forceinline__ float softplusf(float x) {
    return fmaxf(x, 0.f) + log1pf(__expf(-fabsf(x)));
}

// ---------------- KL over all N rows ----------------
__global__ void k_kl(const float* __restrict__ lin_w, const float* __restrict__ lin_b) {
    __shared__ float s_w[D * TSZ];
    __shared__ float s_b[D];
    for (int i = threadIdx.x; i < D * TSZ; i += blockDim.x) s_w[i] = lin_w[i];
    if (threadIdx.x < D) s_b[threadIdx.x] = lin_b[threadIdx.x];
    __syncthreads();

    int row = blockIdx.x * blockDim.x + threadIdx.x;
    double local = 0.0;
    if (row < NN) {
        float m[D];
        const float4* rp = (const float4*)&g_acc[row * D];
#pragma unroll
        for (int i = 0; i < 16; i++) {
            float4 v = rp[i];
            m[4 * i] = v.x; m[4 * i + 1] = v.y; m[4 * i + 2] = v.z; m[4 * i + 3] = v.w;
        }
        float sp[TSZ];
#pragma unroll
        for (int t = 0; t < TSZ; t++) sp[t] = softplusf(m[t]);
        float accl = 0.f;
#pragma unroll
        for (int d = 0; d < D; d++) {
            float s = s_b[d];
#pragma unroll
            for (int t = 0; t < TSZ; t++) s += sp[t] * s_w[d * TSZ + t];
            s += 1e-8f;
            float kl = -0.5f * (1.0f + 2.0f * s - m[d] * m[d] - __expf(2.0f * s));
            if (isfinite(kl)) accl += kl;
        }
        local = (double)accl;
    }
    __shared__ double s_red[256];
    s_red[threadIdx.x] = local;
    __syncthreads();
    for (int off = 128; off > 0; off >>= 1) {
        if (threadIdx.x < off) s_red[threadIdx.x] += s_red[threadIdx.x + off];
        __syncthreads();
    }
    if (threadIdx.x == 0) atomicAdd(&g_sums[0], s_red[0]);
}

// ---------------- batch: gen rows + intent rows, normalized ----------------
__global__ void k_batch(const float* __restrict__ lin_w, const float* __restrict__ lin_b,
                        const float* __restrict__ eps,
                        const float* __restrict__ uint_, const float* __restrict__ iint_,
                        const int* __restrict__ users, const int* __restrict__ pos_items) {
    int b = blockIdx.x;
    int tid = threadIdx.x;
    __shared__ float s_w[D * TSZ];
    __shared__ float s_mean[D], s_sp[TSZ], s_tmp[D], s_p[NINT];
    __shared__ float s_red[128];
    for (int i = tid; i < D * TSZ; i += 128) s_w[i] = lin_w[i];
    __syncthreads();

    for (int pass = 0; pass < 2; pass++) {
        int node = (pass == 0) ? users[b] : (N_USERS + pos_items[b]);
        const float* intent = (pass == 0) ? uint_ : iint_;
        float* e1 = (pass == 0) ? g_e1u : g_e1i;
        float* e2 = (pass == 0) ? g_e2u : g_e2i;

        if (tid < D) s_mean[tid] = g_acc[node * D + tid];
        __syncthreads();
        if (tid < TSZ) s_sp[tid] = softplusf(s_mean[tid]);
        __syncthreads();

        float genv = 0.f;
        if (tid < D) {
            float s = lin_b[tid];
#pragma unroll
            for (int t = 0; t < TSZ; t++) s += s_sp[t] * s_w[tid * TSZ + t];
            s += 1e-8f;
            genv = s_mean[tid] + eps[node * D + tid] * s;
            s_tmp[tid] = genv;
        }
        s_red[tid] = (tid < D) ? genv * genv : 0.f;
        __syncthreads();
        for (int off = 64; off > 0; off >>= 1) {
            if (tid < off) s_red[tid] += s_red[tid + off];
            __syncthreads();
        }
        float nrm = sqrtf(s_red[0]);
        __syncthreads();
        if (tid < D) e1[b * D + tid] = s_tmp[tid] / nrm;

        // logits over 128 intents (tid = intent index)
        float lg = 0.f;
#pragma unroll
        for (int d = 0; d < D; d++) lg += s_mean[d] * intent[d * NINT + tid];
        s_red[tid] = lg;
        __syncthreads();
        for (int off = 64; off > 0; off >>= 1) {
            if (tid < off) s_red[tid] = fmaxf(s_red[tid], s_red[tid + off]);
            __syncthreads();
        }
        float mx = s_red[0];
        __syncthreads();
        float p = __expf(lg - mx);
        s_p[tid] = p;
        s_red[tid] = p;
        __syncthreads();
        for (int off = 64; off > 0; off >>= 1) {
            if (tid < off) s_red[tid] += s_red[tid + off];
            __syncthreads();
        }
        float Z = s_red[0];
        __syncthreads();

        float ov = 0.f;
        if (tid < D) {
            float o = 0.f;
#pragma unroll
            for (int k = 0; k < NINT; k++) o += s_p[k] * intent[tid * NINT + k];
            ov = o / Z;
            s_tmp[tid] = ov;
        }
        s_red[tid] = (tid < D) ? ov * ov : 0.f;
        __syncthreads();
        for (int off = 64; off > 0; off >>= 1) {
            if (tid < off) s_red[tid] += s_red[tid + off];
            __syncthreads();
        }
        float nrm2 = sqrtf(s_red[0]);
        __syncthreads();
        if (tid < D) e2[b * D + tid] = s_tmp[tid] / nrm2;
        __syncthreads();
    }
}

// ---------------- BPR + embedding reg ----------------
__global__ void k_bpr(const float* __restrict__ ue, const float* __restrict__ ie,
                      const int* __restrict__ users, const int* __restrict__ pos,
                      const int* __restrict__ neg) {
    int b = blockIdx.x;
    int tid = threadIdx.x;
    int u = users[b], p = pos[b], ng = neg[b];
    __shared__ float s_red[128];
    float vpos = 0.f, vneg = 0.f, vemb = 0.f;
    if (tid < D) {
        float au = g_acc[u * D + tid];
        float ap = g_acc[(N_USERS + p) * D + tid];
        float an = g_acc[(N_USERS + ng) * D + tid];
        vpos = au * ap;
        vneg = au * an;
        float e0 = ue[u * D + tid], e1v = ie[p * D + tid], e2v = ie[ng * D + tid];
        vemb = e0 * e0 + e1v * e1v + e2v * e2v;
    }
    s_red[tid] = (tid < D) ? vpos : 0.f;
    __syncthreads();
    for (int off = 64; off > 0; off >>= 1) { if (tid < off) s_red[tid] += s_red[tid + off]; __syncthreads(); }
    float ps = s_red[0];
    __syncthreads();
    s_red[tid] = (tid < D) ? vneg : 0.f;
    __syncthreads();
    for (int off = 64; off > 0; off >>= 1) { if (tid < off) s_red[tid] += s_red[tid + off]; __syncthreads(); }
    float ns = s_red[0];
    __syncthreads();
    s_red[tid] = (tid < D) ? vemb : 0.f;
    __syncthreads();
    for (int off = 64; off > 0; off >>= 1) { if (tid < off) s_red[tid] += s_red[tid + off]; __syncthreads(); }
    float es = s_red[0];
    if (tid == 0) {
        float x = ns - ps;
        float sp = softplusf(x);
        atomicAdd(&g_sums[1], (double)sp);
        atomicAdd(&g_sums[2], (double)es);
    }
}

// ---------------- intent L2 reg ----------------
__global__ void k_int(const float* __restrict__ ui, const float* __restrict__ ii) {
    float acc = 0.f;
    for (int i = threadIdx.x; i < D * NINT; i += blockDim.x) {
        float a = ui[i], b = ii[i];
        acc += a * a + b * b;
    }
    __shared__ float s_red[256];
    s_red[threadIdx.x] = acc;
    __syncthreads();
    for (int off = 128; off > 0; off >>= 1) {
        if (threadIdx.x < off) s_red[threadIdx.x] += s_red[threadIdx.x + off];
        __syncthreads();
    }
    if (threadIdx.x == 0) atomicAdd(&g_sums[3], (double)s_red[0]);
}

// ---------------- InfoNCE: 4096x4096x64 with fused exp + rowsum ----------------
__global__ void __launch_bounds__(256) k_nce(int which) {
    const float* __restrict__ e1 = which ? g_e1i : g_e1u;
    const float* __restrict__ e2 = which ? g_e2i : g_e2u;
    __shared__ float s2[128 * 65];
    int tid = threadIdx.x, lane = tid & 31, wid = tid >> 5;
    int b = blockIdx.x * 8 + wid;
    float e1r[64];
#pragma unroll
    for (int d = 0; d < 64; d++) e1r[d] = e1[b * 64 + d];
    float rsum = 0.f, pos = 0.f;
    for (int tile = 0; tile < 32; tile++) {
        __syncthreads();
        for (int i = tid; i < 128 * 64; i += 256) {
            int r = i >> 6, d = i & 63;
            s2[r * 65 + d] = e2[(tile * 128 + r) * 64 + d];
        }
        __syncthreads();
#pragma unroll
        for (int jj = 0; jj < 4; jj++) {
            int jl = jj * 32 + lane;
            float acc = 0.f;
#pragma unroll
            for (int d = 0; d < 64; d++) acc += e1r[d] * s2[jl * 65 + d];
            float ev = __expf(acc * TEMP_INV);
            rsum += ev;
            if (tile * 128 + jl == b) pos = ev;
        }
    }
#pragma unroll
    for (int off = 16; off > 0; off >>= 1) {
        rsum += __shfl_xor_sync(0xffffffffu, rsum, off);
        pos  += __shfl_xor_sync(0xffffffffu, pos, off);
    }
    if (lane == 0) {
        float l = -logf(pos / (rsum + 1e-8f) + 1e-8f);
        atomicAdd(&g_sums[4 + which], (double)l);
    }
}

// ---------------- final combine ----------------
__global__ void k_final(float* __restrict__ out) {
    if (threadIdx.x == 0) {
        double bpr = g_sums[1] / (double)BB;
        double kl  = KL_REG * g_sums[0] / (double)NN;
        out[0] = (float)(bpr + kl);
        out[1] = (float)(SSL_REG * (g_sums[4] / (double)BB + g_sums[5] / (double)BB));
        out[2] = (float)(EMB_REG * g_sums[2]);
        out[3] = (float)(INT_REG * g_sums[3]);
    }
}

// ---------------- launch ----------------
extern "C" void kernel_launch(void* const* d_in, const int* in_sizes, int n_in,
                              void* d_out, int out_size) {
    const float* user_emb  = (const float*)d_in[0];
    const float* item_emb  = (const float*)d_in[1];
    const float* user_int  = (const float*)d_in[2];
    const float* item_int  = (const float*)d_in[3];
    const float* lin_w     = (const float*)d_in[4];
    const float* lin_b     = (const float*)d_in[5];
    const float* eps       = (const float*)d_in[6];
    const int*   h_list    = (const int*)d_in[7];
    const int*   t_list    = (const int*)d_in[8];
    const int*   users     = (const int*)d_in[9];
    const int*   pos_items = (const int*)d_in[10];
    const int*   neg_items = (const int*)d_in[11];
    float* out = (float*)d_out;

    k_init<<<(NN + 255) / 256, 256>>>();
    k_deg<<<(EE + 255) / 256, 256>>>(h_list);
    k_scan1<<<NB, 1024>>>();
    k_scan2<<<1, 32>>>();
    k_scan3<<<(NN + 255) / 256, 256>>>();
    k_scatter<<<(EE + 255) / 256, 256>>>(h_list, t_list);
    k_initemb<<<(NN * D + 255) / 256, 256>>>(user_emb, item_emb);
    k_prop<<<(NN + 7) / 8, 256>>>(0);
    k_prop<<<(NN + 7) / 8, 256>>>(1);
    k_prop<<<(NN + 7) / 8, 256>>>(0);
    k_kl<<<(NN + 255) / 256, 256>>>(lin_w, lin_b);
    k_batch<<<BB, 128>>>(lin_w, lin_b, eps, user_int, item_int, users, pos_items);
    k_bpr<<<BB, 128>>>(user_emb, item_emb, users, pos_items, neg_items);
    k_int<<<1, 256>>>(user_int, item_int);
    k_nce<<<512, 256>>>(0);
    k_nce<<<512, 256>>>(1);
    k_final<<<1, 32>>>(out);
}

// round 3
// speedup vs baseline: 1.3278x; 1.3278x over previous
#include <cuda_runtime.h>
#include <math.h>

#define N_USERS 50000
#define N_ITEMS 100000
#define NN      150000
#define D       64
#define NINT    128
#define TSZ     32
#define BB      4096
#define EE      3150000
#define NB      147            // ceil(NN/1024)
#define TEMP_INV 5.0f
#define KL_REG  0.01
#define EMB_REG 1e-5
#define INT_REG 1e-5
#define SSL_REG 0.1

// ---------------- scratch (static device globals; no runtime alloc) ----------------
__device__ int    g_deg[NN];
__device__ int    g_rowptr[NN + 1];
__device__ int    g_cursor[NN];
__device__ int    g_bsums[256];
__device__ float  g_dinv[NN];
__device__ int    g_tsorted[EE];
__device__ float  g_gsorted[EE];
__device__ float  g_bufA[NN * D];
__device__ float  g_bufB[NN * D];
__device__ float  g_acc[NN * D];
__device__ float  g_e1u[BB * D], g_e2u[BB * D], g_e1i[BB * D], g_e2i[BB * D];
__device__ float  g_rsum[2 * BB];
__device__ float  g_pos[2 * BB];
__device__ double g_sums[8];   // 0:kl 1:bpr 2:emb 3:int 4:nce_u 5:nce_i

// packed f32x2 FMA (FFMA2) — PTX-only on sm_103a
__device__ __forceinline__ unsigned long long fma2(unsigned long long a,
                                                   unsigned long long b,
                                                   unsigned long long c) {
    unsigned long long d;
    asm("fma.rn.f32x2 %0, %1, %2, %3;" : "=l"(d) : "l"(a), "l"(b), "l"(c));
    return d;
}
__device__ __forceinline__ float f2_lo(unsigned long long v) {
    return __int_as_float((int)(unsigned)(v & 0xffffffffull));
}
__device__ __forceinline__ float f2_hi(unsigned long long v) {
    return __int_as_float((int)(unsigned)(v >> 32));
}

// ---------------- degree (g_deg must be zero on entry: BSS init / reset by k_scatter) ----------------
__global__ void k_deg(const int* __restrict__ h) {
    int i = blockIdx.x * blockDim.x + threadIdx.x;
    if (i < EE) atomicAdd(&g_deg[h[i]], 1);
}

// ---------------- 2-level exclusive scan ----------------
__global__ void k_scan1() {
    __shared__ int s[1024];
    int idx = blockIdx.x * 1024 + threadIdx.x;
    int v = (idx < NN) ? g_deg[idx] : 0;
    s[threadIdx.x] = v;
    __syncthreads();
    for (int off = 1; off < 1024; off <<= 1) {
        int t = (threadIdx.x >= off) ? s[threadIdx.x - off] : 0;
        __syncthreads();
        s[threadIdx.x] += t;
        __syncthreads();
    }
    if (idx < NN) g_rowptr[idx] = s[threadIdx.x] - v;   // block-local exclusive
    if (threadIdx.x == 1023) g_bsums[blockIdx.x] = s[1023];
}

__global__ void k_scan2() {   // parallel scan of NB block sums (NB <= 256)
    __shared__ int s[256];
    int i = threadIdx.x;
    int v = (i < NB) ? g_bsums[i] : 0;
    s[i] = v;
    __syncthreads();
    for (int off = 1; off < 256; off <<= 1) {
        int t = (i >= off) ? s[i - off] : 0;
        __syncthreads();
        s[i] += t;
        __syncthreads();
    }
    if (i < NB) g_bsums[i] = s[i] - v;   // exclusive
}

__global__ void k_scan3() {
    int i = blockIdx.x * blockDim.x + threadIdx.x;
    if (i < NN) {
        int rp = g_rowptr[i] + g_bsums[i >> 10];
        g_rowptr[i] = rp;
        g_cursor[i] = rp;
        g_dinv[i]   = 1.0f / sqrtf((float)g_deg[i]);
        if (i == 0) g_rowptr[NN] = EE;
    }
}

// ---------------- CSR scatter (+ reset g_deg for next call) ----------------
__global__ void k_scatter(const int* __restrict__ h, const int* __restrict__ t) {
    int i = blockIdx.x * blockDim.x + threadIdx.x;
    if (i < NN) g_deg[i] = 0;   // consume-and-reset (deg no longer needed)
    if (i < EE) {
        int hh = h[i], tt = t[i];
        int pos = atomicAdd(&g_cursor[hh], 1);
        g_tsorted[pos] = tt;
        g_gsorted[pos] = g_dinv[hh] * g_dinv[tt];
    }
}

// ---------------- ego init + zero nce partials ----------------
__global__ void k_initemb(const float* __restrict__ ue, const float* __restrict__ ie) {
    int i = blockIdx.x * blockDim.x + threadIdx.x;
    if (i < 2 * BB) { g_rsum[i] = 0.f; g_pos[i] = 0.f; }
    if (i < NN * D) {
        float v = (i < N_USERS * D) ? ue[i] : ie[i - N_USERS * D];
        g_bufA[i] = v;
        g_acc[i]  = v;
    }
}

// ---------------- propagation: warp per node, batched edge loads + 4-deep pipelining ----------------
__global__ void __launch_bounds__(256) k_prop(int which) {
    int gw = (blockIdx.x * blockDim.x + threadIdx.x) >> 5;
    int lane = threadIdx.x & 31;
    if (gw >= NN) return;
    const float* __restrict__ cur = which ? g_bufB : g_bufA;
    float* __restrict__ nxt       = which ? g_bufA : g_bufB;
    int beg = g_rowptr[gw], end = g_rowptr[gw + 1];
    float a0 = 0.f, a1 = 0.f;
    for (int base = beg; base < end; base += 32) {
        int rem = end - base; if (rem > 32) rem = 32;
        int tt = 0; float gg = 0.f;
        if (lane < rem) { tt = g_tsorted[base + lane]; gg = g_gsorted[base + lane]; }
        int i = 0;
        for (; i + 4 <= rem; i += 4) {
            int t0 = __shfl_sync(0xffffffffu, tt, i);
            int t1 = __shfl_sync(0xffffffffu, tt, i + 1);
            int t2 = __shfl_sync(0xffffffffu, tt, i + 2);
            int t3 = __shfl_sync(0xffffffffu, tt, i + 3);
            float g0 = __shfl_sync(0xffffffffu, gg, i);
            float g1 = __shfl_sync(0xffffffffu, gg, i + 1);
            float g2 = __shfl_sync(0xffffffffu, gg, i + 2);
            float g3 = __shfl_sync(0xffffffffu, gg, i + 3);
            float2 v0 = *(const float2*)&cur[t0 * D + lane * 2];
            float2 v1 = *(const float2*)&cur[t1 * D + lane * 2];
            float2 v2 = *(const float2*)&cur[t2 * D + lane * 2];
            float2 v3 = *(const float2*)&cur[t3 * D + lane * 2];
            a0 = fmaf(g0, v0.x, a0); a1 = fmaf(g0, v0.y, a1);
            a0 = fmaf(g1, v1.x, a0); a1 = fmaf(g1, v1.y, a1);
            a0 = fmaf(g2, v2.x, a0); a1 = fmaf(g2, v2.y, a1);
            a0 = fmaf(g3, v3.x, a0); a1 = fmaf(g3, v3.y, a1);
        }
        for (; i < rem; i++) {
            int   t = __shfl_sync(0xffffffffu, tt, i);
            float g = __shfl_sync(0xffffffffu, gg, i);
            float2 v = *(const float2*)&cur[t * D + lane * 2];
            a0 = fmaf(g, v.x, a0); a1 = fmaf(g, v.y, a1);
        }
    }
    int o = gw * D + lane * 2;
    nxt[o] = a0; nxt[o + 1] = a1;
    g_acc[o] += a0; g_acc[o + 1] += a1;
}

__device__ __forceinline__ float softplusf(float x) {
    return fmaxf(x, 0.f) + log1pf(__expf(-fabsf(x)));
}

// ---------------- KL over all N rows ----------------
__global__ void k_kl(const float* __restrict__ lin_w, const float* __restrict__ lin_b) {
    __shared__ float s_w[D * TSZ];
    __shared__ float s_b[D];
    for (int i = threadIdx.x; i < D * TSZ; i += blockDim.x) s_w[i] = lin_w[i];
    if (threadIdx.x < D) s_b[threadIdx.x] = lin_b[threadIdx.x];
    __syncthreads();

    int row = blockIdx.x * blockDim.x + threadIdx.x;
    double local = 0.0;
    if (row < NN) {
        float m[D];
        const float4* rp = (const float4*)&g_acc[row * D];
#pragma unroll
        for (int i = 0; i < 16; i++) {
            float4 v = rp[i];
            m[4 * i] = v.x; m[4 * i + 1] = v.y; m[4 * i + 2] = v.z; m[4 * i + 3] = v.w;
        }
        float sp[TSZ];
#pragma unroll
        for (int t = 0; t < TSZ; t++) sp[t] = softplusf(m[t]);
        float accl = 0.f;
#pragma unroll
        for (int d = 0; d < D; d++) {
            float s = s_b[d];
#pragma unroll
            for (int t = 0; t < TSZ; t++) s += sp[t] * s_w[d * TSZ + t];
            s += 1e-8f;
            float kl = -0.5f * (1.0f + 2.0f * s - m[d] * m[d] - __expf(2.0f * s));
            if (isfinite(kl)) accl += kl;
        }
        local = (double)accl;
    }
    __shared__ double s_red[256];
    s_red[threadIdx.x] = local;
    __syncthreads();
    for (int off = 128; off > 0; off >>= 1) {
        if (threadIdx.x < off) s_red[threadIdx.x] += s_red[threadIdx.x + off];
        __syncthreads();
    }
    if (threadIdx.x == 0) atomicAdd(&g_sums[0], s_red[0]);
}

// ---------------- batch: gen rows + intent rows, normalized ----------------
__global__ void k_batch(const float* __restrict__ lin_w, const float* __restrict__ lin_b,
                        const float* __restrict__ eps,
                        const float* __restrict__ uint_, const float* __restrict__ iint_,
                        const int* __restrict__ users, const int* __restrict__ pos_items) {
    int b = blockIdx.x;
    int tid = threadIdx.x;
    __shared__ float s_w[D * TSZ];
    __shared__ float s_mean[D], s_sp[TSZ], s_tmp[D], s_p[NINT];
    __shared__ float s_red[128];
    for (int i = tid; i < D * TSZ; i += 128) s_w[i] = lin_w[i];
    __syncthreads();

    for (int pass = 0; pass < 2; pass++) {
        int node = (pass == 0) ? users[b] : (N_USERS + pos_items[b]);
        const float* intent = (pass == 0) ? uint_ : iint_;
        float* e1 = (pass == 0) ? g_e1u : g_e1i;
        float* e2 = (pass == 0) ? g_e2u : g_e2i;

        if (tid < D) s_mean[tid] = g_acc[node * D + tid];
        __syncthreads();
        if (tid < TSZ) s_sp[tid] = softplusf(s_mean[tid]);
        __syncthreads();

        float genv = 0.f;
        if (tid < D) {
            float s = lin_b[tid];
#pragma unroll
            for (int t = 0; t < TSZ; t++) s += s_sp[t] * s_w[tid * TSZ + t];
            s += 1e-8f;
            genv = s_mean[tid] + eps[node * D + tid] * s;
            s_tmp[tid] = genv;
        }
        s_red[tid] = (tid < D) ? genv * genv : 0.f;
        __syncthreads();
        for (int off = 64; off > 0; off >>= 1) {
            if (tid < off) s_red[tid] += s_red[tid + off];
            __syncthreads();
        }
        float nrm = sqrtf(s_red[0]);
        __syncthreads();
        if (tid < D) e1[b * D + tid] = s_tmp[tid] / nrm;

        float lg = 0.f;
#pragma unroll
        for (int d = 0; d < D; d++) lg += s_mean[d] * intent[d * NINT + tid];
        s_red[tid] = lg;
        __syncthreads();
        for (int off = 64; off > 0; off >>= 1) {
            if (tid < off) s_red[tid] = fmaxf(s_red[tid], s_red[tid + off]);
            __syncthreads();
        }
        float mx = s_red[0];
        __syncthreads();
        float p = __expf(lg - mx);
        s_p[tid] = p;
        s_red[tid] = p;
        __syncthreads();
        for (int off = 64; off > 0; off >>= 1) {
            if (tid < off) s_red[tid] += s_red[tid + off];
            __syncthreads();
        }
        float Z = s_red[0];
        __syncthreads();

        float ov = 0.f;
        if (tid < D) {
            float o = 0.f;
#pragma unroll
            for (int k = 0; k < NINT; k++) o += s_p[k] * intent[tid * NINT + k];
            ov = o / Z;
            s_tmp[tid] = ov;
        }
        s_red[tid] = (tid < D) ? ov * ov : 0.f;
        __syncthreads();
        for (int off = 64; off > 0; off >>= 1) {
            if (tid < off) s_red[tid] += s_red[tid + off];
            __syncthreads();
        }
        float nrm2 = sqrtf(s_red[0]);
        __syncthreads();
        if (tid < D) e2[b * D + tid] = s_tmp[tid] / nrm2;
        __syncthreads();
    }
}

// ---------------- BPR + embedding reg ----------------
__global__ void k_bpr(const float* __restrict__ ue, const float* __restrict__ ie,
                      const int* __restrict__ users, const int* __restrict__ pos,
                      const int* __restrict__ neg) {
    int b = blockIdx.x;
    int tid = threadIdx.x;
    int u = users[b], p = pos[b], ng = neg[b];
    __shared__ float s_red[128];
    float vpos = 0.f, vneg = 0.f, vemb = 0.f;
    if (tid < D) {
        float au = g_acc[u * D + tid];
        float ap = g_acc[(N_USERS + p) * D + tid];
        float an = g_acc[(N_USERS + ng) * D + tid];
        vpos = au * ap;
        vneg = au * an;
        float e0 = ue[u * D + tid], e1v = ie[p * D + tid], e2v = ie[ng * D + tid];
        vemb = e0 * e0 + e1v * e1v + e2v * e2v;
    }
    s_red[tid] = (tid < D) ? vpos : 0.f;
    __syncthreads();
    for (int off = 64; off > 0; off >>= 1) { if (tid < off) s_red[tid] += s_red[tid + off]; __syncthreads(); }
    float ps = s_red[0];
    __syncthreads();
    s_red[tid] = (tid < D) ? vneg : 0.f;
    __syncthreads();
    for (int off = 64; off > 0; off >>= 1) { if (tid < off) s_red[tid] += s_red[tid + off]; __syncthreads(); }
    float ns = s_red[0];
    __syncthreads();
    s_red[tid] = (tid < D) ? vemb : 0.f;
    __syncthreads();
    for (int off = 64; off > 0; off >>= 1) { if (tid < off) s_red[tid] += s_red[tid + off]; __syncthreads(); }
    float es = s_red[0];
    if (tid == 0) {
        float x = ns - ps;
        float sp = softplusf(x);
        atomicAdd(&g_sums[1], (double)sp);
        atomicAdd(&g_sums[2], (double)es);
    }
}

// ---------------- intent L2 reg ----------------
__global__ void k_int(const float* __restrict__ ui, const float* __restrict__ ii) {
    float acc = 0.f;
    for (int i = threadIdx.x; i < D * NINT; i += blockDim.x) {
        float a = ui[i], b = ii[i];
        acc += a * a + b * b;
    }
    __shared__ float s_red[256];
    s_red[threadIdx.x] = acc;
    __syncthreads();
    for (int off = 128; off > 0; off >>= 1) {
        if (threadIdx.x < off) s_red[threadIdx.x] += s_red[threadIdx.x + off];
        __syncthreads();
    }
    if (threadIdx.x == 0) atomicAdd(&g_sums[3], (double)s_red[0]);
}

// ---------------- InfoNCE GEMM: FFMA2 register tiling ----------------
// grid (4 colsplits, 128 rowblocks, 2 which), block 128 threads (4 warps).
// Block: 32 rows x 1024 cols. Warp: 8 rows; lane covers cols {32j+lane : j=0..3} per 128-col tile.
__global__ void __launch_bounds__(128, 3) k_nce(int dummy) {
    int which = blockIdx.z;
    const float* __restrict__ e1 = which ? g_e1i : g_e1u;
    const float* __restrict__ e2 = which ? g_e2i : g_e2u;

    __shared__ float e1s[32 * 64];      // row-major [r][64]
    __shared__ float e2s[128 * 68];     // row-major [c][68] (pad => 4*lane bank mapping)

    int tid  = threadIdx.x;
    int lane = tid & 31;
    int wid  = tid >> 5;
    int rbase = blockIdx.y * 32;
    int csbase = blockIdx.x * 1024;

    // stage e1 rows (once)
#pragma unroll
    for (int it = 0; it < 16; it++) {
        int flat = it * 128 + tid;          // 0..2047
        e1s[flat] = e1[rbase * 64 + flat];
    }

    unsigned long long acc[8][4];
    float rsumr[8], posr[8];
#pragma unroll
    for (int r = 0; r < 8; r++) { rsumr[r] = 0.f; posr[r] = 0.f; }

    int gr[8];
#pragma unroll
    for (int r = 0; r < 8; r++) gr[r] = rbase + wid * 8 + r;

    for (int tile = 0; tile < 8; tile++) {
        int tb = csbase + tile * 128;
        __syncthreads();
        // stage e2 tile: 128 cols x 64 d as float4
#pragma unroll
        for (int it = 0; it < 16; it++) {
            int flat = it * 128 + tid;      // 0..2047 float4 units
            int c = flat >> 4, d4 = flat & 15;
            *(float4*)&e2s[c * 68 + d4 * 4] = *(const float4*)&e2[(tb + c) * 64 + d4 * 4];
        }
        __syncthreads();

#pragma unroll
        for (int r = 0; r < 8; r++)
#pragma unroll
            for (int j = 0; j < 4; j++) acc[r][j] = 0ull;

#pragma unroll
        for (int d4 = 0; d4 < 16; d4++) {
            ulonglong2 B0 = *(const ulonglong2*)&e2s[(0 * 32 + lane) * 68 + d4 * 4];
            ulonglong2 B1 = *(const ulonglong2*)&e2s[(1 * 32 + lane) * 68 + d4 * 4];
            ulonglong2 B2 = *(const ulonglong2*)&e2s[(2 * 32 + lane) * 68 + d4 * 4];
            ulonglong2 B3 = *(const ulonglong2*)&e2s[(3 * 32 + lane) * 68 + d4 * 4];
#pragma unroll
            for (int r = 0; r < 8; r++) {
                ulonglong2 A = *(const ulonglong2*)&e1s[(wid * 8 + r) * 64 + d4 * 4];
                acc[r][0] = fma2(A.x, B0.x, acc[r][0]);
                acc[r][1] = fma2(A.x, B1.x, acc[r][1]);
                acc[r][2] = fma2(A.x, B2.x, acc[r][2]);
                acc[r][3] = fma2(A.x, B3.x, acc[r][3]);
                acc[r][0] = fma2(A.y, B0.y, acc[r][0]);
                acc[r][1] = fma2(A.y, B1.y, acc[r][1]);
                acc[r][2] = fma2(A.y, B2.y, acc[r][2]);
                acc[r][3] = fma2(A.y, B3.y, acc[r][3]);
            }
        }

        // epilogue: exp + row-sum
#pragma unroll
        for (int r = 0; r < 8; r++) {
#pragma unroll
            for (int j = 0; j < 4; j++) {
                float s = f2_lo(acc[r][j]) + f2_hi(acc[r][j]);
                float ev = __expf(s * TEMP_INV);
                rsumr[r] += ev;
                int gc = tb + j * 32 + lane;
                if (gc == gr[r]) posr[r] = ev;
            }
        }
    }

    // reduce across lanes, commit partials
#pragma unroll
    for (int r = 0; r < 8; r++) {
        float rs = rsumr[r], ps = posr[r];
#pragma unroll
        for (int off = 16; off > 0; off >>= 1) {
            rs += __shfl_xor_sync(0xffffffffu, rs, off);
            ps += __shfl_xor_sync(0xffffffffu, ps, off);
        }
        if (lane == 0) {
            atomicAdd(&g_rsum[which * BB + gr[r]], rs);
            atomicAdd(&g_pos[which * BB + gr[r]], ps);
        }
    }
}

// ---------------- InfoNCE final reduce ----------------
__global__ void k_nce_red() {
    int which = blockIdx.x;
    double s = 0.0;
    for (int r = threadIdx.x; r < BB; r += 256) {
        float rs = g_rsum[which * BB + r];
        float p  = g_pos[which * BB + r];
        s += (double)(-logf(p / (rs + 1e-8f) + 1e-8f));
    }
    __shared__ double s_red[256];
    s_red[threadIdx.x] = s;
    __syncthreads();
    for (int off = 128; off > 0; off >>= 1) {
        if (threadIdx.x < off) s_red[threadIdx.x] += s_red[threadIdx.x + off];
        __syncthreads();
    }
    if (threadIdx.x == 0) atomicAdd(&g_sums[4 + which], s_red[0]);
}

// ---------------- final combine (+ reset sums for next call) ----------------
__global__ void k_final(float* __restrict__ out) {
    if (threadIdx.x == 0) {
        double bpr = g_sums[1] / (double)BB;
        double kl  = KL_REG * g_sums[0] / (double)NN;
        out[0] = (float)(bpr + kl);
        out[1] = (float)(SSL_REG * (g_sums[4] / (double)BB + g_sums[5] / (double)BB));
        out[2] = (float)(EMB_REG * g_sums[2]);
        out[3] = (float)(INT_REG * g_sums[3]);
        for (int i = 0; i < 8; i++) g_sums[i] = 0.0;
    }
}

// ---------------- launch ----------------
extern "C" void kernel_launch(void* const* d_in, const int* in_sizes, int n_in,
                              void* d_out, int out_size) {
    const float* user_emb  = (const float*)d_in[0];
    const float* item_emb  = (const float*)d_in[1];
    const float* user_int  = (const float*)d_in[2];
    const float* item_int  = (const float*)d_in[3];
    const float* lin_w     = (const float*)d_in[4];
    const float* lin_b     = (const float*)d_in[5];
    const float* eps       = (const float*)d_in[6];
    const int*   h_list    = (const int*)d_in[7];
    const int*   t_list    = (const int*)d_in[8];
    const int*   users     = (const int*)d_in[9];
    const int*   pos_items = (const int*)d_in[10];
    const int*   neg_items = (const int*)d_in[11];
    float* out = (float*)d_out;

    k_deg<<<(EE + 255) / 256, 256>>>(h_list);
    k_scan1<<<NB, 1024>>>();
    k_scan2<<<1, 256>>>();
    k_scan3<<<(NN + 255) / 256, 256>>>();
    k_scatter<<<(EE + 255) / 256, 256>>>(h_list, t_list);
    k_initemb<<<(NN * D + 255) / 256, 256>>>(user_emb, item_emb);
    k_prop<<<(NN + 7) / 8, 256>>>(0);
    k_prop<<<(NN + 7) / 8, 256>>>(1);
    k_prop<<<(NN + 7) / 8, 256>>>(0);
    k_kl<<<(NN + 255) / 256, 256>>>(lin_w, lin_b);
    k_batch<<<BB, 128>>>(lin_w, lin_b, eps, user_int, item_int, users, pos_items);
    k_bpr<<<BB, 128>>>(user_emb, item_emb, users, pos_items, neg_items);
    k_int<<<1, 256>>>(user_int, item_int);
    k_nce<<<dim3(4, 128, 2), 128>>>(0);
    k_nce_red<<<2, 256>>>();
    k_final<<<1, 32>>>(out);
}

// round 4
// speedup vs baseline: 1.4249x; 1.0731x over previous
#include <cuda_runtime.h>
#include <cuda_bf16.h>
#include <math.h>

#define N_USERS 50000
#define N_ITEMS 100000
#define NN      150000
#define D       64
#define NINT    128
#define TSZ     32
#define BB      4096
#define EE      3150000
#define NB      147            // ceil(NN/1024)
#define TEMP_INV 5.0f
#define KL_REG  0.01
#define EMB_REG 1e-5
#define INT_REG 1e-5
#define SSL_REG 0.1

// ---------------- scratch (static device globals; no runtime alloc) ----------------
__device__ int    g_deg[NN];
__device__ int    g_rowptr[NN + 1];
__device__ int    g_cursor[NN];
__device__ int    g_bsums[256];
__device__ float  g_dinv[NN];
__device__ int    g_tsorted[EE];
__device__ float  g_gsorted[EE];
__device__ __nv_bfloat16 g_bufA[NN * D];
__device__ __nv_bfloat16 g_bufB[NN * D];
__device__ float  g_acc[NN * D];
__device__ float  g_e1u[BB * D], g_e2u[BB * D], g_e1i[BB * D], g_e2i[BB * D];
__device__ float  g_rsum[2 * BB];
__device__ float  g_pos[2 * BB];
__device__ double g_sums[8];   // 0:kl 1:bpr 2:emb 3:int 4:nce_u 5:nce_i

// packed f32x2 FMA (FFMA2) — PTX-only on sm_103a
__device__ __forceinline__ unsigned long long fma2(unsigned long long a,
                                                   unsigned long long b,
                                                   unsigned long long c) {
    unsigned long long d;
    asm("fma.rn.f32x2 %0, %1, %2, %3;" : "=l"(d) : "l"(a), "l"(b), "l"(c));
    return d;
}
__device__ __forceinline__ float f2_lo(unsigned long long v) {
    return __int_as_float((int)(unsigned)(v & 0xffffffffull));
}
__device__ __forceinline__ float f2_hi(unsigned long long v) {
    return __int_as_float((int)(unsigned)(v >> 32));
}

// ---------------- degree (g_deg must be zero on entry: BSS init / reset by k_scatter) ----------------
__global__ void k_deg(const int* __restrict__ h) {
    int i = blockIdx.x * blockDim.x + threadIdx.x;
    if (i < EE) atomicAdd(&g_deg[h[i]], 1);
}

// ---------------- 2-level exclusive scan ----------------
__global__ void k_scan1() {
    __shared__ int s[1024];
    int idx = blockIdx.x * 1024 + threadIdx.x;
    int v = (idx < NN) ? g_deg[idx] : 0;
    s[threadIdx.x] = v;
    __syncthreads();
    for (int off = 1; off < 1024; off <<= 1) {
        int t = (threadIdx.x >= off) ? s[threadIdx.x - off] : 0;
        __syncthreads();
        s[threadIdx.x] += t;
        __syncthreads();
    }
    if (idx < NN) g_rowptr[idx] = s[threadIdx.x] - v;   // block-local exclusive
    if (threadIdx.x == 1023) g_bsums[blockIdx.x] = s[1023];
}

__global__ void k_scan2() {   // parallel scan of NB block sums (NB <= 256)
    __shared__ int s[256];
    int i = threadIdx.x;
    int v = (i < NB) ? g_bsums[i] : 0;
    s[i] = v;
    __syncthreads();
    for (int off = 1; off < 256; off <<= 1) {
        int t = (i >= off) ? s[i - off] : 0;
        __syncthreads();
        s[i] += t;
        __syncthreads();
    }
    if (i < NB) g_bsums[i] = s[i] - v;   // exclusive
}

__global__ void k_scan3() {
    int i = blockIdx.x * blockDim.x + threadIdx.x;
    if (i < NN) {
        int rp = g_rowptr[i] + g_bsums[i >> 10];
        g_rowptr[i] = rp;
        g_cursor[i] = rp;
        g_dinv[i]   = 1.0f / sqrtf((float)g_deg[i]);
        if (i == 0) g_rowptr[NN] = EE;
    }
}

// ---------------- CSR scatter (+ reset g_deg for next call) ----------------
__global__ void k_scatter(const int* __restrict__ h, const int* __restrict__ t) {
    int i = blockIdx.x * blockDim.x + threadIdx.x;
    if (i < NN) g_deg[i] = 0;   // consume-and-reset (deg no longer needed)
    if (i < EE) {
        int hh = h[i], tt = t[i];
        int pos = atomicAdd(&g_cursor[hh], 1);
        g_tsorted[pos] = tt;
        g_gsorted[pos] = g_dinv[hh] * g_dinv[tt];
    }
}

// ---------------- ego init (fp32 acc + bf16 cur) + zero nce partials ----------------
__global__ void k_initemb(const float* __restrict__ ue, const float* __restrict__ ie) {
    int i = blockIdx.x * blockDim.x + threadIdx.x;
    if (i < 2 * BB) { g_rsum[i] = 0.f; g_pos[i] = 0.f; }
    if (i < NN * D) {
        float v = (i < N_USERS * D) ? ue[i] : ie[i - N_USERS * D];
        g_bufA[i] = __float2bfloat16(v);
        g_acc[i]  = v;
    }
}

// ---------------- propagation: warp per node, bf16 gather, fp32 accumulate ----------------
__global__ void __launch_bounds__(256) k_prop(int which) {
    int gw = (blockIdx.x * blockDim.x + threadIdx.x) >> 5;
    int lane = threadIdx.x & 31;
    if (gw >= NN) return;
    const __nv_bfloat16* __restrict__ cur = which ? g_bufB : g_bufA;
    __nv_bfloat16* __restrict__ nxt       = which ? g_bufA : g_bufB;
    int beg = g_rowptr[gw], end = g_rowptr[gw + 1];
    float a0 = 0.f, a1 = 0.f;
    for (int base = beg; base < end; base += 32) {
        int rem = end - base; if (rem > 32) rem = 32;
        int tt = 0; float gg = 0.f;
        if (lane < rem) { tt = g_tsorted[base + lane]; gg = g_gsorted[base + lane]; }
        int i = 0;
        for (; i + 4 <= rem; i += 4) {
            int t0 = __shfl_sync(0xffffffffu, tt, i);
            int t1 = __shfl_sync(0xffffffffu, tt, i + 1);
            int t2 = __shfl_sync(0xffffffffu, tt, i + 2);
            int t3 = __shfl_sync(0xffffffffu, tt, i + 3);
            float g0 = __shfl_sync(0xffffffffu, gg, i);
            float g1 = __shfl_sync(0xffffffffu, gg, i + 1);
            float g2 = __shfl_sync(0xffffffffu, gg, i + 2);
            float g3 = __shfl_sync(0xffffffffu, gg, i + 3);
            float2 v0 = __bfloat1622float2(*(const __nv_bfloat162*)&cur[t0 * D + lane * 2]);
            float2 v1 = __bfloat1622float2(*(const __nv_bfloat162*)&cur[t1 * D + lane * 2]);
            float2 v2 = __bfloat1622float2(*(const __nv_bfloat162*)&cur[t2 * D + lane * 2]);
            float2 v3 = __bfloat1622float2(*(const __nv_bfloat162*)&cur[t3 * D + lane * 2]);
            a0 = fmaf(g0, v0.x, a0); a1 = fmaf(g0, v0.y, a1);
            a0 = fmaf(g1, v1.x, a0); a1 = fmaf(g1, v1.y, a1);
            a0 = fmaf(g2, v2.x, a0); a1 = fmaf(g2, v2.y, a1);
            a0 = fmaf(g3, v3.x, a0); a1 = fmaf(g3, v3.y, a1);
        }
        for (; i < rem; i++) {
            int   t = __shfl_sync(0xffffffffu, tt, i);
            float g = __shfl_sync(0xffffffffu, gg, i);
            float2 v = __bfloat1622float2(*(const __nv_bfloat162*)&cur[t * D + lane * 2]);
            a0 = fmaf(g, v.x, a0); a1 = fmaf(g, v.y, a1);
        }
    }
    int o = gw * D + lane * 2;
    *(__nv_bfloat162*)&nxt[o] = __float22bfloat162_rn(make_float2(a0, a1));
    g_acc[o] += a0; g_acc[o + 1] += a1;
}

__device__ __forceinline__ float softplusf(float x) {
    return fmaxf(x, 0.f) + log1pf(__expf(-fabsf(x)));
}

// ---------------- KL over all N rows ----------------
__global__ void k_kl(const float* __restrict__ lin_w, const float* __restrict__ lin_b) {
    __shared__ float s_w[D * TSZ];
    __shared__ float s_b[D];
    for (int i = threadIdx.x; i < D * TSZ; i += blockDim.x) s_w[i] = lin_w[i];
    if (threadIdx.x < D) s_b[threadIdx.x] = lin_b[threadIdx.x];
    __syncthreads();

    int row = blockIdx.x * blockDim.x + threadIdx.x;
    double local = 0.0;
    if (row < NN) {
        float m[D];
        const float4* rp = (const float4*)&g_acc[row * D];
#pragma unroll
        for (int i = 0; i < 16; i++) {
            float4 v = rp[i];
            m[4 * i] = v.x; m[4 * i + 1] = v.y; m[4 * i + 2] = v.z; m[4 * i + 3] = v.w;
        }
        float sp[TSZ];
#pragma unroll
        for (int t = 0; t < TSZ; t++) sp[t] = softplusf(m[t]);
        float accl = 0.f;
#pragma unroll
        for (int d = 0; d < D; d++) {
            float s = s_b[d];
#pragma unroll
            for (int t = 0; t < TSZ; t++) s += sp[t] * s_w[d * TSZ + t];
            s += 1e-8f;
            float kl = -0.5f * (1.0f + 2.0f * s - m[d] * m[d] - __expf(2.0f * s));
            if (isfinite(kl)) accl += kl;
        }
        local = (double)accl;
    }
    __shared__ double s_red[256];
    s_red[threadIdx.x] = local;
    __syncthreads();
    for (int off = 128; off > 0; off >>= 1) {
        if (threadIdx.x < off) s_red[threadIdx.x] += s_red[threadIdx.x + off];
        __syncthreads();
    }
    if (threadIdx.x == 0) atomicAdd(&g_sums[0], s_red[0]);
}

// ---------------- batch: gen rows + intent rows, normalized ----------------
__global__ void k_batch(const float* __restrict__ lin_w, const float* __restrict__ lin_b,
                        const float* __restrict__ eps,
                        const float* __restrict__ uint_, const float* __restrict__ iint_,
                        const int* __restrict__ users, const int* __restrict__ pos_items) {
    int b = blockIdx.x;
    int tid = threadIdx.x;
    __shared__ float s_w[D * TSZ];
    __shared__ float s_mean[D], s_sp[TSZ], s_tmp[D], s_p[NINT];
    __shared__ float s_red[128];
    for (int i = tid; i < D * TSZ; i += 128) s_w[i] = lin_w[i];
    __syncthreads();

    for (int pass = 0; pass < 2; pass++) {
        int node = (pass == 0) ? users[b] : (N_USERS + pos_items[b]);
        const float* intent = (pass == 0) ? uint_ : iint_;
        float* e1 = (pass == 0) ? g_e1u : g_e1i;
        float* e2 = (pass == 0) ? g_e2u : g_e2i;

        if (tid < D) s_mean[tid] = g_acc[node * D + tid];
        __syncthreads();
        if (tid < TSZ) s_sp[tid] = softplusf(s_mean[tid]);
        __syncthreads();

        float genv = 0.f;
        if (tid < D) {
            float s = lin_b[tid];
#pragma unroll
            for (int t = 0; t < TSZ; t++) s += s_sp[t] * s_w[tid * TSZ + t];
            s += 1e-8f;
            genv = s_mean[tid] + eps[node * D + tid] * s;
            s_tmp[tid] = genv;
        }
        s_red[tid] = (tid < D) ? genv * genv : 0.f;
        __syncthreads();
        for (int off = 64; off > 0; off >>= 1) {
            if (tid < off) s_red[tid] += s_red[tid + off];
            __syncthreads();
        }
        float nrm = sqrtf(s_red[0]);
        __syncthreads();
        if (tid < D) e1[b * D + tid] = s_tmp[tid] / nrm;

        float lg = 0.f;
#pragma unroll
        for (int d = 0; d < D; d++) lg += s_mean[d] * intent[d * NINT + tid];
        s_red[tid] = lg;
        __syncthreads();
        for (int off = 64; off > 0; off >>= 1) {
            if (tid < off) s_red[tid] = fmaxf(s_red[tid], s_red[tid + off]);
            __syncthreads();
        }
        float mx = s_red[0];
        __syncthreads();
        float p = __expf(lg - mx);
        s_p[tid] = p;
        s_red[tid] = p;
        __syncthreads();
        for (int off = 64; off > 0; off >>= 1) {
            if (tid < off) s_red[tid] += s_red[tid + off];
            __syncthreads();
        }
        float Z = s_red[0];
        __syncthreads();

        float ov = 0.f;
        if (tid < D) {
            float o = 0.f;
#pragma unroll
            for (int k = 0; k < NINT; k++) o += s_p[k] * intent[tid * NINT + k];
            ov = o / Z;
            s_tmp[tid] = ov;
        }
        s_red[tid] = (tid < D) ? ov * ov : 0.f;
        __syncthreads();
        for (int off = 64; off > 0; off >>= 1) {
            if (tid < off) s_red[tid] += s_red[tid + off];
            __syncthreads();
        }
        float nrm2 = sqrtf(s_red[0]);
        __syncthreads();
        if (tid < D) e2[b * D + tid] = s_tmp[tid] / nrm2;
        __syncthreads();
    }
}

// ---------------- BPR + embedding reg ----------------
__global__ void k_bpr(const float* __restrict__ ue, const float* __restrict__ ie,
                      const int* __restrict__ users, const int* __restrict__ pos,
                      const int* __restrict__ neg) {
    int b = blockIdx.x;
    int tid = threadIdx.x;
    int u = users[b], p = pos[b], ng = neg[b];
    __shared__ float s_red[128];
    float vpos = 0.f, vneg = 0.f, vemb = 0.f;
    if (tid < D) {
        float au = g_acc[u * D + tid];
        float ap = g_acc[(N_USERS + p) * D + tid];
        float an = g_acc[(N_USERS + ng) * D + tid];
        vpos = au * ap;
        vneg = au * an;
        float e0 = ue[u * D + tid], e1v = ie[p * D + tid], e2v = ie[ng * D + tid];
        vemb = e0 * e0 + e1v * e1v + e2v * e2v;
    }
    s_red[tid] = (tid < D) ? vpos : 0.f;
    __syncthreads();
    for (int off = 64; off > 0; off >>= 1) { if (tid < off) s_red[tid] += s_red[tid + off]; __syncthreads(); }
    float ps = s_red[0];
    __syncthreads();
    s_red[tid] = (tid < D) ? vneg : 0.f;
    __syncthreads();
    for (int off = 64; off > 0; off >>= 1) { if (tid < off) s_red[tid] += s_red[tid + off]; __syncthreads(); }
    float ns = s_red[0];
    __syncthreads();
    s_red[tid] = (tid < D) ? vemb : 0.f;
    __syncthreads();
    for (int off = 64; off > 0; off >>= 1) { if (tid < off) s_red[tid] += s_red[tid + off]; __syncthreads(); }
    float es = s_red[0];
    if (tid == 0) {
        float x = ns - ps;
        float sp = softplusf(x);
        atomicAdd(&g_sums[1], (double)sp);
        atomicAdd(&g_sums[2], (double)es);
    }
}

// ---------------- intent L2 reg ----------------
__global__ void k_int(const float* __restrict__ ui, const float* __restrict__ ii) {
    float acc = 0.f;
    for (int i = threadIdx.x; i < D * NINT; i += blockDim.x) {
        float a = ui[i], b = ii[i];
        acc += a * a + b * b;
    }
    __shared__ float s_red[256];
    s_red[threadIdx.x] = acc;
    __syncthreads();
    for (int off = 128; off > 0; off >>= 1) {
        if (threadIdx.x < off) s_red[threadIdx.x] += s_red[threadIdx.x + off];
        __syncthreads();
    }
    if (threadIdx.x == 0) atomicAdd(&g_sums[3], (double)s_red[0]);
}

// ---------------- InfoNCE GEMM: FFMA2 register tiling ----------------
__global__ void __launch_bounds__(128, 3) k_nce(int dummy) {
    int which = blockIdx.z;
    const float* __restrict__ e1 = which ? g_e1i : g_e1u;
    const float* __restrict__ e2 = which ? g_e2i : g_e2u;

    __shared__ float e1s[32 * 64];
    __shared__ float e2s[128 * 68];

    int tid  = threadIdx.x;
    int lane = tid & 31;
    int wid  = tid >> 5;
    int rbase = blockIdx.y * 32;
    int csbase = blockIdx.x * 1024;

#pragma unroll
    for (int it = 0; it < 16; it++) {
        int flat = it * 128 + tid;
        e1s[flat] = e1[rbase * 64 + flat];
    }

    unsigned long long acc[8][4];
    float rsumr[8], posr[8];
#pragma unroll
    for (int r = 0; r < 8; r++) { rsumr[r] = 0.f; posr[r] = 0.f; }

    int gr[8];
#pragma unroll
    for (int r = 0; r < 8; r++) gr[r] = rbase + wid * 8 + r;

    for (int tile = 0; tile < 8; tile++) {
        int tb = csbase + tile * 128;
        __syncthreads();
#pragma unroll
        for (int it = 0; it < 16; it++) {
            int flat = it * 128 + tid;
            int c = flat >> 4, d4 = flat & 15;
            *(float4*)&e2s[c * 68 + d4 * 4] = *(const float4*)&e2[(tb + c) * 64 + d4 * 4];
        }
        __syncthreads();

#pragma unroll
        for (int r = 0; r < 8; r++)
#pragma unroll
            for (int j = 0; j < 4; j++) acc[r][j] = 0ull;

#pragma unroll
        for (int d4 = 0; d4 < 16; d4++) {
            ulonglong2 B0 = *(const ulonglong2*)&e2s[(0 * 32 + lane) * 68 + d4 * 4];
            ulonglong2 B1 = *(const ulonglong2*)&e2s[(1 * 32 + lane) * 68 + d4 * 4];
            ulonglong2 B2 = *(const ulonglong2*)&e2s[(2 * 32 + lane) * 68 + d4 * 4];
            ulonglong2 B3 = *(const ulonglong2*)&e2s[(3 * 32 + lane) * 68 + d4 * 4];
#pragma unroll
            for (int r = 0; r < 8; r++) {
                ulonglong2 A = *(const ulonglong2*)&e1s[(wid * 8 + r) * 64 + d4 * 4];
                acc[r][0] = fma2(A.x, B0.x, acc[r][0]);
                acc[r][1] = fma2(A.x, B1.x, acc[r][1]);
                acc[r][2] = fma2(A.x, B2.x, acc[r][2]);
                acc[r][3] = fma2(A.x, B3.x, acc[r][3]);
                acc[r][0] = fma2(A.y, B0.y, acc[r][0]);
                acc[r][1] = fma2(A.y, B1.y, acc[r][1]);
                acc[r][2] = fma2(A.y, B2.y, acc[r][2]);
                acc[r][3] = fma2(A.y, B3.y, acc[r][3]);
            }
        }

#pragma unroll
        for (int r = 0; r < 8; r++) {
#pragma unroll
            for (int j = 0; j < 4; j++) {
                float s = f2_lo(acc[r][j]) + f2_hi(acc[r][j]);
                float ev = __expf(s * TEMP_INV);
                rsumr[r] += ev;
                int gc = tb + j * 32 + lane;
                if (gc == gr[r]) posr[r] = ev;
            }
        }
    }

#pragma unroll
    for (int r = 0; r < 8; r++) {
        float rs = rsumr[r], ps = posr[r];
#pragma unroll
        for (int off = 16; off > 0; off >>= 1) {
            rs += __shfl_xor_sync(0xffffffffu, rs, off);
            ps += __shfl_xor_sync(0xffffffffu, ps, off);
        }
        if (lane == 0) {
            atomicAdd(&g_rsum[which * BB + gr[r]], rs);
            atomicAdd(&g_pos[which * BB + gr[r]], ps);
        }
    }
}

// ---------------- InfoNCE final reduce ----------------
__global__ void k_nce_red() {
    int which = blockIdx.x;
    double s = 0.0;
    for (int r = threadIdx.x; r < BB; r += 256) {
        float rs = g_rsum[which * BB + r];
        float p  = g_pos[which * BB + r];
        s += (double)(-logf(p / (rs + 1e-8f) + 1e-8f));
    }
    __shared__ double s_red[256];
    s_red[threadIdx.x] = s;
    __syncthreads();
    for (int off = 128; off > 0; off >>= 1) {
        if (threadIdx.x < off) s_red[threadIdx.x] += s_red[threadIdx.x + off];
        __syncthreads();
    }
    if (threadIdx.x == 0) atomicAdd(&g_sums[4 + which], s_red[0]);
}

// ---------------- final combine (+ reset sums for next call) ----------------
__global__ void k_final(float* __restrict__ out) {
    if (threadIdx.x == 0) {
        double bpr = g_sums[1] / (double)BB;
        double kl  = KL_REG * g_sums[0] / (double)NN;
        out[0] = (float)(bpr + kl);
        out[1] = (float)(SSL_REG * (g_sums[4] / (double)BB + g_sums[5] / (double)BB));
        out[2] = (float)(EMB_REG * g_sums[2]);
        out[3] = (float)(INT_REG * g_sums[3]);
        for (int i = 0; i < 8; i++) g_sums[i] = 0.0;
    }
}

// ---------------- launch ----------------
extern "C" void kernel_launch(void* const* d_in, const int* in_sizes, int n_in,
                              void* d_out, int out_size) {
    const float* user_emb  = (const float*)d_in[0];
    const float* item_emb  = (const float*)d_in[1];
    const float* user_int  = (const float*)d_in[2];
    const float* item_int  = (const float*)d_in[3];
    const float* lin_w     = (const float*)d_in[4];
    const float* lin_b     = (const float*)d_in[5];
    const float* eps       = (const float*)d_in[6];
    const int*   h_list    = (const int*)d_in[7];
    const int*   t_list    = (const int*)d_in[8];
    const int*   users     = (const int*)d_in[9];
    const int*   pos_items = (const int*)d_in[10];
    const int*   neg_items = (const int*)d_in[11];
    float* out = (float*)d_out;

    k_deg<<<(EE + 255) / 256, 256>>>(h_list);
    k_scan1<<<NB, 1024>>>();
    k_scan2<<<1, 256>>>();
    k_scan3<<<(NN + 255) / 256, 256>>>();
    k_scatter<<<(EE + 255) / 256, 256>>>(h_list, t_list);
    k_initemb<<<(NN * D + 255) / 256, 256>>>(user_emb, item_emb);
    k_prop<<<(NN + 7) / 8, 256>>>(0);
    k_prop<<<(NN + 7) / 8, 256>>>(1);
    k_prop<<<(NN + 7) / 8, 256>>>(0);
    k_kl<<<(NN + 255) / 256, 256>>>(lin_w, lin_b);
    k_batch<<<BB, 128>>>(lin_w, lin_b, eps, user_int, item_int, users, pos_items);
    k_bpr<<<BB, 128>>>(user_emb, item_emb, users, pos_items, neg_items);
    k_int<<<1, 256>>>(user_int, item_int);
    k_nce<<<dim3(4, 128, 2), 128>>>(0);
    k_nce_red<<<2, 256>>>();
    k_final<<<1, 32>>>(out);
}